// round 9
// baseline (speedup 1.0000x reference)
#include <cuda_runtime.h>
#include <cstdint>

#define NH 8
#define TT 256
#define DHD 64
#define DD 512
#define NSPLIT 8

// ---------------- scratch (static __device__, allocation-free) ----------------
__device__ float g_heads[5][NH][TT][DHD];          // k1,k2,q,v1,v2
__device__ float g_Wq[NH][TT][DHD * DHD];          // [h][q][k*64+j]
__device__ float g_S[NH][TT][TT][TT];              // [h][q][p][t]
__device__ float g_T1[NH][TT][TT][DHD];            // [h][q][p][c]
__device__ float g_R[NH][TT][DHD * DHD];           // [h][q][a*64+c]
__device__ float g_pmax[NH][TT][4];                // per-64-stripe max of S
__device__ float g_psum[NH][TT][4];                // per-128-stripe sum of exp
__device__ float g_zp[NSPLIT][NH][4][64][64];      // z split-K partials
__device__ float g_z[TT][DD];                      // attention output

// ============================ TF32 MMA machinery ==============================
__device__ __forceinline__ float to_tf32(float x) {
    uint32_t u; asm("cvt.rna.tf32.f32 %0, %1;" : "=r"(u) : "f"(x));
    return __uint_as_float(u);
}
__device__ __forceinline__ void mma8(float* c, float a0, float a1, float a2, float a3,
                                     float b0, float b1) {
    asm volatile(
        "mma.sync.aligned.m16n8k8.row.col.f32.tf32.tf32.f32 "
        "{%0,%1,%2,%3},{%4,%5,%6,%7},{%8,%9},{%0,%1,%2,%3};"
        : "+f"(c[0]), "+f"(c[1]), "+f"(c[2]), "+f"(c[3])
        : "r"(__float_as_uint(a0)), "r"(__float_as_uint(a1)),
          "r"(__float_as_uint(a2)), "r"(__float_as_uint(a3)),
          "r"(__float_as_uint(b0)), "r"(__float_as_uint(b1)));
}
// ---- 16x32 warp tile (plain), As[m][k] pad 68, Bs[k][n] pad 72 (wq, aq phase1)
__device__ __forceinline__ void wtile(const float (*As)[68], const float (*Bs)[72],
                                      float acc[4][4], int m0, int n0, int gid, int tig) {
#pragma unroll
    for (int kc = 0; kc < 64; kc += 8) {
        float a0 = As[m0 + gid][kc + tig],     a1 = As[m0 + gid + 8][kc + tig];
        float a2 = As[m0 + gid][kc + tig + 4], a3 = As[m0 + gid + 8][kc + tig + 4];
#pragma unroll
        for (int nt = 0; nt < 4; nt++) {
            int n = n0 + nt * 8;
            mma8(acc[nt], a0, a1, a2, a3, Bs[kc + tig][n + gid], Bs[kc + tig + 4][n + gid]);
        }
    }
}
// ---- 16x32 warp tile 3xTF32 (zp) --------------------------------------------
__device__ __forceinline__ void wtile3(const float (*Ah)[68], const float (*Al)[68],
                                       const float (*Bh)[72], const float (*Bl)[72],
                                       float acc[4][4], int m0, int n0, int gid, int tig) {
#pragma unroll
    for (int kc = 0; kc < 64; kc += 8) {
        float ah0 = Ah[m0 + gid][kc + tig],     ah1 = Ah[m0 + gid + 8][kc + tig];
        float ah2 = Ah[m0 + gid][kc + tig + 4], ah3 = Ah[m0 + gid + 8][kc + tig + 4];
        float al0 = Al[m0 + gid][kc + tig],     al1 = Al[m0 + gid + 8][kc + tig];
        float al2 = Al[m0 + gid][kc + tig + 4], al3 = Al[m0 + gid + 8][kc + tig + 4];
#pragma unroll
        for (int nt = 0; nt < 4; nt++) {
            int n = n0 + nt * 8;
            float bh0 = Bh[kc + tig][n + gid], bh1 = Bh[kc + tig + 4][n + gid];
            float bl0 = Bl[kc + tig][n + gid], bl1 = Bl[kc + tig + 4][n + gid];
            mma8(acc[nt], ah0, ah1, ah2, ah3, bh0, bh1);
            mma8(acc[nt], al0, al1, al2, al3, bh0, bh1);
            mma8(acc[nt], ah0, ah1, ah2, ah3, bl0, bl1);
        }
    }
}
// ---- 32x32 warp tile (plain), templated B pad (aqattn phase 2) ---------------
template<int BP>
__device__ __forceinline__ void wtile32(const float (*As)[68], const float (*Bs)[BP],
                                        float acc[2][4][4], int m0, int n0, int gid, int tig) {
#pragma unroll
    for (int kc = 0; kc < 64; kc += 8) {
        float a[2][4];
#pragma unroll
        for (int mi = 0; mi < 2; mi++) {
            int m = m0 + mi * 16;
            a[mi][0] = As[m + gid][kc + tig];
            a[mi][1] = As[m + gid + 8][kc + tig];
            a[mi][2] = As[m + gid][kc + tig + 4];
            a[mi][3] = As[m + gid + 8][kc + tig + 4];
        }
#pragma unroll
        for (int nt = 0; nt < 4; nt++) {
            int n = n0 + nt * 8;
            float b0 = Bs[kc + tig][n + gid], b1 = Bs[kc + tig + 4][n + gid];
            mma8(acc[0][nt], a[0][0], a[0][1], a[0][2], a[0][3], b0, b1);
            mma8(acc[1][nt], a[1][0], a[1][1], a[1][2], a[1][3], b0, b1);
        }
    }
}
// ---- 32x32 warp tile 3xTF32, templated B pad (t1, r) -------------------------
template<int BP>
__device__ __forceinline__ void wtile32_3(const float (*Ah)[68], const float (*Al)[68],
                                          const float (*Bh)[BP], const float (*Bl)[BP],
                                          float acc[2][4][4], int m0, int n0, int gid, int tig) {
#pragma unroll
    for (int kc = 0; kc < 64; kc += 8) {
        float ah[2][4], al[2][4];
#pragma unroll
        for (int mi = 0; mi < 2; mi++) {
            int m = m0 + mi * 16;
            ah[mi][0] = Ah[m + gid][kc + tig];
            ah[mi][1] = Ah[m + gid + 8][kc + tig];
            ah[mi][2] = Ah[m + gid][kc + tig + 4];
            ah[mi][3] = Ah[m + gid + 8][kc + tig + 4];
            al[mi][0] = Al[m + gid][kc + tig];
            al[mi][1] = Al[m + gid + 8][kc + tig];
            al[mi][2] = Al[m + gid][kc + tig + 4];
            al[mi][3] = Al[m + gid + 8][kc + tig + 4];
        }
#pragma unroll
        for (int nt = 0; nt < 4; nt++) {
            int n = n0 + nt * 8;
            float bh0 = Bh[kc + tig][n + gid], bh1 = Bh[kc + tig + 4][n + gid];
            float bl0 = Bl[kc + tig][n + gid], bl1 = Bl[kc + tig + 4][n + gid];
#pragma unroll
            for (int mi = 0; mi < 2; mi++) {
                mma8(acc[mi][nt], ah[mi][0], ah[mi][1], ah[mi][2], ah[mi][3], bh0, bh1);
                mma8(acc[mi][nt], al[mi][0], al[mi][1], al[mi][2], al[mi][3], bh0, bh1);
                mma8(acc[mi][nt], ah[mi][0], ah[mi][1], ah[mi][2], ah[mi][3], bl0, bl1);
            }
        }
    }
}
// gmem [m][k] -> As[m][k] (tf32), 64x64, 256 threads
__device__ __forceinline__ void ldA(const float* __restrict__ src, int lda,
                                    float (*As)[68], int tid) {
#pragma unroll
    for (int i = 0; i < 4; i++) {
        int id = tid + i * 256, r = id >> 4, c = (id & 15) << 2;
        float4 v = *reinterpret_cast<const float4*>(src + (long)r * lda + c);
        float4 w = {to_tf32(v.x), to_tf32(v.y), to_tf32(v.z), to_tf32(v.w)};
        *reinterpret_cast<float4*>(&As[r][c]) = w;
    }
}
// gmem [k][n] -> Bs[k][n] (tf32)
__device__ __forceinline__ void ldB(const float* __restrict__ src, int ldb,
                                    float (*Bs)[72], int tid) {
#pragma unroll
    for (int i = 0; i < 4; i++) {
        int id = tid + i * 256, r = id >> 4, c = (id & 15) << 2;
        float4 v = *reinterpret_cast<const float4*>(src + (long)r * ldb + c);
        float4 w = {to_tf32(v.x), to_tf32(v.y), to_tf32(v.z), to_tf32(v.w)};
        *reinterpret_cast<float4*>(&Bs[r][c]) = w;
    }
}
// gmem [n][k] -> Bs[k][n] (tf32)
__device__ __forceinline__ void ldBt(const float* __restrict__ src, int ldbt,
                                     float (*Bs)[72], int tid) {
#pragma unroll
    for (int i = 0; i < 4; i++) {
        int id = tid + i * 256, n = id & 63, kb = (id >> 6) << 2;
        float4 v = *reinterpret_cast<const float4*>(src + (long)n * ldbt + kb);
        Bs[kb][n] = to_tf32(v.x); Bs[kb + 1][n] = to_tf32(v.y);
        Bs[kb + 2][n] = to_tf32(v.z); Bs[kb + 3][n] = to_tf32(v.w);
    }
}
// split: hi = tf32(x), lo = tf32(x - hi)
__device__ __forceinline__ void split1(float x, float& h, float& l) {
    h = to_tf32(x); l = to_tf32(x - h);
}
__device__ __forceinline__ void ldA_split(const float* __restrict__ src, int lda,
                                          float (*Ah)[68], float (*Al)[68], int tid) {
#pragma unroll
    for (int i = 0; i < 4; i++) {
        int id = tid + i * 256, r = id >> 4, c = (id & 15) << 2;
        float4 v = *reinterpret_cast<const float4*>(src + (long)r * lda + c);
        float4 h, l;
        split1(v.x, h.x, l.x); split1(v.y, h.y, l.y);
        split1(v.z, h.z, l.z); split1(v.w, h.w, l.w);
        *reinterpret_cast<float4*>(&Ah[r][c]) = h;
        *reinterpret_cast<float4*>(&Al[r][c]) = l;
    }
}
// gmem [k][m] -> As[m][k] split (transposed scatter), 64x64
__device__ __forceinline__ void ldAt_split(const float* __restrict__ src, int ldx,
                                           float (*Ah)[68], float (*Al)[68], int tid) {
#pragma unroll
    for (int i = 0; i < 4; i++) {
        int id = tid + i * 256, k = id & 63, mb = (id >> 6) << 2;
        float4 v = *reinterpret_cast<const float4*>(src + (long)k * ldx + mb);
        float h, l;
        split1(v.x, h, l); Ah[mb][k] = h;     Al[mb][k] = l;
        split1(v.y, h, l); Ah[mb + 1][k] = h; Al[mb + 1][k] = l;
        split1(v.z, h, l); Ah[mb + 2][k] = h; Al[mb + 2][k] = l;
        split1(v.w, h, l); Ah[mb + 3][k] = h; Al[mb + 3][k] = l;
    }
}
__device__ __forceinline__ void ldB_split(const float* __restrict__ src, int ldb,
                                          float (*Bh)[72], float (*Bl)[72], int tid) {
#pragma unroll
    for (int i = 0; i < 4; i++) {
        int id = tid + i * 256, r = id >> 4, c = (id & 15) << 2;
        float4 v = *reinterpret_cast<const float4*>(src + (long)r * ldb + c);
        float4 h, l;
        split1(v.x, h.x, l.x); split1(v.y, h.y, l.y);
        split1(v.z, h.z, l.z); split1(v.w, h.w, l.w);
        *reinterpret_cast<float4*>(&Bh[r][c]) = h;
        *reinterpret_cast<float4*>(&Bl[r][c]) = l;
    }
}
// 16x32 store (wq, zp)
__device__ __forceinline__ void store_tile(float* C, int ldc, const float acc[4][4],
                                           int m0, int n0, int gid, int tig) {
#pragma unroll
    for (int nt = 0; nt < 4; nt++) {
        int n = n0 + nt * 8 + 2 * tig;
        *reinterpret_cast<float2*>(C + (long)(m0 + gid) * ldc + n) =
            make_float2(acc[nt][0], acc[nt][1]);
        *reinterpret_cast<float2*>(C + (long)(m0 + gid + 8) * ldc + n) =
            make_float2(acc[nt][2], acc[nt][3]);
    }
}

// smem layouts (float offsets)
#define ZP_AH 0
#define ZP_AL (64 * 68)
#define ZP_BH (2 * 64 * 68)
#define ZP_BL (2 * 64 * 68 + 64 * 72)
#define ZP_SMEM ((2 * 64 * 68 + 2 * 64 * 72) * 4)         // 71680 B

#define AQ_AQS 0
#define AQ_AS  (64 * 68)
#define AQ_BS  (2 * 64 * 68)
#define AQ_B2  (64 * 68)                                   // phase2 B overlaps AS..BS
#define AQ_SMEM ((2 * 64 * 68 + 64 * 72) * 4)              // 53248 B

#define T1_AH 0
#define T1_AL (128 * 68)
#define T1_BH (2 * 128 * 68)
#define T1_BL (2 * 128 * 68 + 64 * 72)
#define T1_SMEM ((2 * 128 * 68 + 2 * 64 * 72) * 4)         // 106496 B

#define R_AH 0
#define R_AL (64 * 68)
#define R_BH (2 * 64 * 68)
#define R_BL (2 * 64 * 68 + 64 * 136)
#define R_SMEM ((2 * 64 * 68 + 2 * 64 * 136) * 4)          // 104448 B

// ===================== FFMA 64x64 tile (proj/out only) ========================
__device__ __forceinline__ void f_loadAT(const float* __restrict__ A, int lda,
                                         float As[64][68], int tid) {
#pragma unroll
    for (int i = 0; i < 4; i++) {
        int id = tid + i * 256, r = id >> 4, c = (id & 15) << 2;
        float4 v = *reinterpret_cast<const float4*>(A + (long)r * lda + c);
        As[c][r] = v.x; As[c + 1][r] = v.y; As[c + 2][r] = v.z; As[c + 3][r] = v.w;
    }
}
__device__ __forceinline__ void f_loadB(const float* __restrict__ B, int ldb,
                                        float Bs[64][68], int tid) {
#pragma unroll
    for (int i = 0; i < 4; i++) {
        int id = tid + i * 256, r = id >> 4, c = (id & 15) << 2;
        float4 v = *reinterpret_cast<const float4*>(B + (long)r * ldb + c);
        *reinterpret_cast<float4*>(&Bs[r][c]) = v;
    }
}
__device__ __forceinline__ void f_mma(const float As[64][68], const float Bs[64][68],
                                      float acc[4][4], int tm, int tn) {
#pragma unroll
    for (int k = 0; k < 64; k++) {
        float4 a = *reinterpret_cast<const float4*>(&As[k][tm * 4]);
        float4 b = *reinterpret_cast<const float4*>(&Bs[k][tn * 4]);
        acc[0][0] += a.x * b.x; acc[0][1] += a.x * b.y; acc[0][2] += a.x * b.z; acc[0][3] += a.x * b.w;
        acc[1][0] += a.y * b.x; acc[1][1] += a.y * b.y; acc[1][2] += a.y * b.z; acc[1][3] += a.y * b.w;
        acc[2][0] += a.z * b.x; acc[2][1] += a.z * b.y; acc[2][2] += a.z * b.z; acc[2][3] += a.z * b.w;
        acc[3][0] += a.w * b.x; acc[3][1] += a.w * b.y; acc[3][2] += a.w * b.z; acc[3][3] += a.w * b.w;
    }
}

// ---------------- K0: proj = x @ W_kkqvv + b (fp32 FFMA), scatter -------------
__global__ __launch_bounds__(256) void proj_kernel(const float* __restrict__ x,
                                                   const float* __restrict__ W,
                                                   const float* __restrict__ bias) {
    __shared__ float As[64][68];
    __shared__ float Bs[64][68];
    int tid = threadIdx.x, tm = tid >> 4, tn = tid & 15;
    int n0 = blockIdx.x * 64, m0 = blockIdx.y * 64;
    float acc[4][4] = {};
    for (int k0 = 0; k0 < DD; k0 += 64) {
        f_loadAT(x + (long)m0 * DD + k0, DD, As, tid);
        f_loadB(W + (long)k0 * (5 * DD) + n0, 5 * DD, Bs, tid);
        __syncthreads();
        f_mma(As, Bs, acc, tm, tn);
        __syncthreads();
    }
#pragma unroll
    for (int r = 0; r < 4; r++)
#pragma unroll
        for (int c = 0; c < 4; c++) {
            int row = m0 + tm * 4 + r;
            int col = n0 + tn * 4 + c;
            float v = acc[r][c] + bias[col];
            int part = col >> 9;
            int rem = col & 511;
            g_heads[part][rem >> 6][row][rem & 63] = v;
        }
}

// ---------------- K1: Wq = q @ W_Kq^T (tf32, 16x32) ---------------------------
__global__ __launch_bounds__(256) void wq_kernel(const float* __restrict__ WKq) {
    __shared__ float As[64][68];
    __shared__ float Bs[64][72];
    int tid = threadIdx.x, w = tid >> 5, lane = tid & 31;
    int gid = lane >> 2, tig = lane & 3;
    int m0 = (w & 3) * 16, n0 = (w >> 2) * 32;
    int kj0 = blockIdx.x * 64, q0 = blockIdx.y * 64, h = blockIdx.z;
    ldA(&g_heads[2][h][q0][0], 64, As, tid);                 // q [q][i]
    ldBt(WKq + ((long)h * 4096 + kj0) * 64, 64, Bs, tid);    // [kj][i] -> [i][kj]
    __syncthreads();
    float acc[4][4] = {};
    wtile(As, Bs, acc, m0, n0, gid, tig);
    store_tile(&g_Wq[h][q0][kj0], 4096, acc, m0, n0, gid, tig);
}

// ---- K2 (fused, tf32): Aq in smem, then S in 64x128 passes (32x32 tiles) -----
__global__ __launch_bounds__(256) void aqattn_kernel() {
    int pt = blockIdx.x, q = blockIdx.y, h = blockIdx.z;
    int qt = q >> 6;
    if (pt > qt) return;
    extern __shared__ float sm[];
    float (*AqS)[68] = reinterpret_cast<float (*)[68]>(sm + AQ_AQS);
    float (*As)[68]  = reinterpret_cast<float (*)[68]>(sm + AQ_AS);
    float (*Bs)[72]  = reinterpret_cast<float (*)[72]>(sm + AQ_BS);
    float (*B2)[136] = reinterpret_cast<float (*)[136]>(sm + AQ_B2);
    __shared__ float red[256];
    int tid = threadIdx.x, w = tid >> 5, lane = tid & 31;
    int gid = lane >> 2, tig = lane & 3;
    int p0 = pt << 6;

    // phase 1: Aq[p][j] = k1[p][k] @ Wq[k][j]  (8 warps, 16x32)
    {
        int m1 = (w & 3) * 16, n1 = (w >> 2) * 32;
        ldA(&g_heads[0][h][p0][0], 64, As, tid);
        ldB(&g_Wq[h][q][0], 64, Bs, tid);
        __syncthreads();
        float accA[4][4] = {};
        wtile(As, Bs, accA, m1, n1, gid, tig);
        __syncthreads();
#pragma unroll
        for (int nt = 0; nt < 4; nt++) {
            int n = n1 + nt * 8 + 2 * tig;
            AqS[m1 + gid][n]     = to_tf32(accA[nt][0]);
            AqS[m1 + gid][n + 1] = to_tf32(accA[nt][1]);
            AqS[m1 + gid + 8][n]     = to_tf32(accA[nt][2]);
            AqS[m1 + gid + 8][n + 1] = to_tf32(accA[nt][3]);
        }
        __syncthreads();
    }

    // phase 2: S[p][t] over two t-tiles per pass; warps 32x32 over 64x128
    int m0 = (w & 1) * 32, n0 = (w >> 1) * 32;
    float vmax = -3.0e38f;
    float* C = &g_S[h][q][0][0];
    int npairs = (qt >> 1) + 1;
    for (int tt2 = 0; tt2 < npairs; tt2++) {
        int t0 = tt2 * 128;
        // load k2 [t0..t0+127][j] -> B2[j][t'] (tf32)
#pragma unroll
        for (int i = 0; i < 8; i++) {
            int id = tid + i * 256, n = id & 127, kb = (id >> 7) << 2;
            float4 v = *reinterpret_cast<const float4*>(&g_heads[1][h][t0 + n][kb]);
            B2[kb][n]     = to_tf32(v.x); B2[kb + 1][n] = to_tf32(v.y);
            B2[kb + 2][n] = to_tf32(v.z); B2[kb + 3][n] = to_tf32(v.w);
        }
        __syncthreads();
        float acc[2][4][4] = {};
        wtile32<136>(AqS, B2, acc, m0, n0, gid, tig);
#pragma unroll
        for (int mi = 0; mi < 2; mi++)
#pragma unroll
            for (int nt = 0; nt < 4; nt++) {
                int plo = p0 + m0 + mi * 16 + gid, phi = plo + 8;
                int t = t0 + n0 + nt * 8 + 2 * tig;
                float v00 = (plo > q || t > q)     ? -1e30f : acc[mi][nt][0] * (1.0f / 64.0f);
                float v01 = (plo > q || t + 1 > q) ? -1e30f : acc[mi][nt][1] * (1.0f / 64.0f);
                float v10 = (phi > q || t > q)     ? -1e30f : acc[mi][nt][2] * (1.0f / 64.0f);
                float v11 = (phi > q || t + 1 > q) ? -1e30f : acc[mi][nt][3] * (1.0f / 64.0f);
                *reinterpret_cast<float2*>(C + (long)plo * TT + t) = make_float2(v00, v01);
                *reinterpret_cast<float2*>(C + (long)phi * TT + t) = make_float2(v10, v11);
                vmax = fmaxf(vmax, fmaxf(fmaxf(v00, v01), fmaxf(v10, v11)));
            }
        __syncthreads();
    }
    red[tid] = vmax;
    __syncthreads();
    for (int off = 128; off > 0; off >>= 1) {
        if (tid < off) red[tid] = fmaxf(red[tid], red[tid + off]);
        __syncthreads();
    }
    if (tid == 0) g_pmax[h][q][pt] = red[0];
}

// ---- K3 (fused softmax + PV step 1, 3xTF32): T1 = exp(S-M) @ v2 --------------
// block: 128 p-rows x 64 c, 8 warps 32x32
__global__ __launch_bounds__(256) void t1_kernel() {
    int pt2 = blockIdx.x, q = blockIdx.y, h = blockIdx.z;
    int qt = q >> 6;
    if (pt2 == 1 && q < 128) return;
    extern __shared__ float sm[];
    float (*Ah)[68] = reinterpret_cast<float (*)[68]>(sm + T1_AH);
    float (*Al)[68] = reinterpret_cast<float (*)[68]>(sm + T1_AL);
    float (*Bh)[72] = reinterpret_cast<float (*)[72]>(sm + T1_BH);
    float (*Bl)[72] = reinterpret_cast<float (*)[72]>(sm + T1_BL);
    __shared__ float red[256];
    int tid = threadIdx.x, w = tid >> 5, lane = tid & 31;
    int gid = lane >> 2, tig = lane & 3;
    int m0 = (w & 3) * 32, n0 = (w >> 2) * 32;
    int p0 = pt2 << 7;

    float M = g_pmax[h][q][0];
    for (int pp = 1; pp <= qt; pp++) M = fmaxf(M, g_pmax[h][q][pp]);

    const float* Pm = &g_S[h][q][p0][0];
    float lsum = 0.0f;
    float acc[2][4][4] = {};
    for (int ks = 0; ks <= qt; ks++) {
        // A := split(exp(S - M)), rows p > q forced to 0 (S there may be unwritten)
#pragma unroll
        for (int i = 0; i < 8; i++) {
            int id = tid + i * 256, r = id >> 4, c = (id & 15) << 2;
            float4 e = {0.0f, 0.0f, 0.0f, 0.0f};
            if (p0 + r <= q) {
                float4 v = *reinterpret_cast<const float4*>(Pm + (long)r * TT + ks * 64 + c);
                e.x = __expf(v.x - M); e.y = __expf(v.y - M);
                e.z = __expf(v.z - M); e.w = __expf(v.w - M);
                lsum += (e.x + e.y) + (e.z + e.w);
            }
            float hh, ll;
            split1(e.x, hh, ll); Ah[r][c] = hh;     Al[r][c] = ll;
            split1(e.y, hh, ll); Ah[r][c + 1] = hh; Al[r][c + 1] = ll;
            split1(e.z, hh, ll); Ah[r][c + 2] = hh; Al[r][c + 2] = ll;
            split1(e.w, hh, ll); Ah[r][c + 3] = hh; Al[r][c + 3] = ll;
        }
        ldB_split(&g_heads[4][h][ks * 64][0], 64, Bh, Bl, tid);    // v2 [t][c]
        __syncthreads();
        wtile32_3<72>(Ah, Al, Bh, Bl, acc, m0, n0, gid, tig);
        __syncthreads();
    }
#pragma unroll
    for (int mi = 0; mi < 2; mi++)
#pragma unroll
        for (int nt = 0; nt < 4; nt++) {
            int r = m0 + mi * 16 + gid;
            int c = n0 + nt * 8 + 2 * tig;
            *reinterpret_cast<float2*>(&g_T1[h][q][p0 + r][c]) =
                make_float2(acc[mi][nt][0], acc[mi][nt][1]);
            *reinterpret_cast<float2*>(&g_T1[h][q][p0 + r + 8][c]) =
                make_float2(acc[mi][nt][2], acc[mi][nt][3]);
        }
    red[tid] = lsum;
    __syncthreads();
    for (int off = 128; off > 0; off >>= 1) {
        if (tid < off) red[tid] += red[tid + off];
        __syncthreads();
    }
    if (tid == 0) g_psum[h][q][pt2] = red[0];
}

// ---- K4 (3xTF32): R[a][c] = sum_p v1[p][a] * T1[p][c], TWO q's per block -----
// block: 64 a-rows x 128 (two q's x 64 c), 8 warps 32x32
__global__ __launch_bounds__(256) void r_kernel() {
    int qb = blockIdx.x, h = blockIdx.y;
    int q0 = qb << 1;
    int qt = q0 >> 6;
    extern __shared__ float sm[];
    float (*Ah)[68]  = reinterpret_cast<float (*)[68]>(sm + R_AH);
    float (*Al)[68]  = reinterpret_cast<float (*)[68]>(sm + R_AL);
    float (*Bh)[136] = reinterpret_cast<float (*)[136]>(sm + R_BH);
    float (*Bl)[136] = reinterpret_cast<float (*)[136]>(sm + R_BL);
    int tid = threadIdx.x, w = tid >> 5, lane = tid & 31;
    int gid = lane >> 2, tig = lane & 3;
    int m0 = (w & 1) * 32, n0 = (w >> 1) * 32;
    float acc[2][4][4] = {};
    for (int ks = 0; ks <= qt; ks++) {
        ldAt_split(&g_heads[3][h][ks * 64][0], 64, Ah, Al, tid);   // v1 [p][a] -> [a][p]
        // B: [p][c'] with c' = qsel*64 + c
#pragma unroll
        for (int i = 0; i < 8; i++) {
            int id = tid + i * 256, r = id >> 5, c = (id & 31) << 2;
            int qsel = c >> 6, cc = c & 63;
            float4 v = *reinterpret_cast<const float4*>(&g_T1[h][q0 + qsel][ks * 64 + r][cc]);
            float hh, ll;
            split1(v.x, hh, ll); Bh[r][c] = hh;     Bl[r][c] = ll;
            split1(v.y, hh, ll); Bh[r][c + 1] = hh; Bl[r][c + 1] = ll;
            split1(v.z, hh, ll); Bh[r][c + 2] = hh; Bl[r][c + 2] = ll;
            split1(v.w, hh, ll); Bh[r][c + 3] = hh; Bl[r][c + 3] = ll;
        }
        __syncthreads();
        wtile32_3<136>(Ah, Al, Bh, Bl, acc, m0, n0, gid, tig);
        __syncthreads();
    }
#pragma unroll
    for (int mi = 0; mi < 2; mi++)
#pragma unroll
        for (int nt = 0; nt < 4; nt++) {
            int a = m0 + mi * 16 + gid;
            int cp = n0 + nt * 8 + 2 * tig;
            int qsel = cp >> 6, cc = cp & 63;
            *reinterpret_cast<float2*>(&g_R[h][q0 + qsel][a * 64 + cc]) =
                make_float2(acc[mi][nt][0], acc[mi][nt][1]);
            *reinterpret_cast<float2*>(&g_R[h][q0 + qsel][(a + 8) * 64 + cc]) =
                make_float2(acc[mi][nt][2], acc[mi][nt][3]);
        }
}

// ---------------- K5 (3xTF32, 16x32): z_part = R @ W_Vq (split-K) -------------
__global__ __launch_bounds__(256) void zp_kernel(const float* __restrict__ WVq) {
    extern __shared__ float sm[];
    float (*Ah)[68] = reinterpret_cast<float (*)[68]>(sm + ZP_AH);
    float (*Al)[68] = reinterpret_cast<float (*)[68]>(sm + ZP_AL);
    float (*Bh)[72] = reinterpret_cast<float (*)[72]>(sm + ZP_BH);
    float (*Bl)[72] = reinterpret_cast<float (*)[72]>(sm + ZP_BL);
    int tid = threadIdx.x, w = tid >> 5, lane = tid & 31;
    int gid = lane >> 2, tig = lane & 3;
    int m0 = (w & 3) * 16, n0 = (w >> 2) * 32;
    int sp = blockIdx.x, qt = blockIdx.y, h = blockIdx.z;
    int q0 = qt << 6;
    int ac0 = sp * (4096 / NSPLIT);
    float acc[4][4] = {};
    for (int ks = 0; ks < 4096 / NSPLIT / 64; ks++) {
        ldA_split(&g_R[h][q0][0] + ac0 + ks * 64, 4096, Ah, Al, tid);
        ldB_split(WVq + ((long)h * 4096 + ac0 + ks * 64) * 64, 64, Bh, Bl, tid);
        __syncthreads();
        wtile3(Ah, Al, Bh, Bl, acc, m0, n0, gid, tig);
        __syncthreads();
    }
    store_tile(&g_zp[sp][h][qt][0][0], 64, acc, m0, n0, gid, tig);
}

// ---------------- K6: reduce split-K, divide by rowsum ------------------------
__global__ __launch_bounds__(256) void zred_kernel() {
    int idx = blockIdx.x * 256 + threadIdx.x;  // 256*512
    int q = idx >> 9, col = idx & 511;
    int h = col >> 6;
    int qt = q >> 6, ql = q & 63;
    int e = col & 63;
    float s = 0.0f;
#pragma unroll
    for (int sp = 0; sp < NSPLIT; sp++) s += g_zp[sp][h][qt][ql][e];
    float rs = g_psum[h][q][0];
    if (qt >= 2) rs += g_psum[h][q][1];
    g_z[q][col] = s / rs;
}

// ---------------- K7: out = z @ W_out + b_out (fp32 FFMA) ---------------------
__global__ __launch_bounds__(256) void out_kernel(const float* __restrict__ Wout,
                                                  const float* __restrict__ bout,
                                                  float* __restrict__ out) {
    __shared__ float As[64][68];
    __shared__ float Bs[64][68];
    int tid = threadIdx.x, tm = tid >> 4, tn = tid & 15;
    int n0 = blockIdx.x * 64, m0 = blockIdx.y * 64;
    float acc[4][4] = {};
    for (int k0 = 0; k0 < DD; k0 += 64) {
        f_loadAT(&g_z[m0][k0], DD, As, tid);
        f_loadB(Wout + (long)k0 * DD + n0, DD, Bs, tid);
        __syncthreads();
        f_mma(As, Bs, acc, tm, tn);
        __syncthreads();
    }
#pragma unroll
    for (int r = 0; r < 4; r++)
#pragma unroll
        for (int c = 0; c < 4; c++) {
            int row = m0 + tm * 4 + r;
            int col = n0 + tn * 4 + c;
            out[(long)row * DD + col] = acc[r][c] + bout[col];
        }
}

// ---------------- launch ------------------------------------------------------
extern "C" void kernel_launch(void* const* d_in, const int* in_sizes, int n_in,
                              void* d_out, int out_size) {
    const float* x    = (const float*)d_in[0];
    const float* Wkk  = (const float*)d_in[1];
    const float* bkk  = (const float*)d_in[2];
    const float* WKq  = (const float*)d_in[3];
    const float* WVq  = (const float*)d_in[4];
    const float* Wout = (const float*)d_in[5];
    const float* bout = (const float*)d_in[6];
    float* out = (float*)d_out;

    cudaFuncSetAttribute(aqattn_kernel, cudaFuncAttributeMaxDynamicSharedMemorySize, AQ_SMEM);
    cudaFuncSetAttribute(t1_kernel,     cudaFuncAttributeMaxDynamicSharedMemorySize, T1_SMEM);
    cudaFuncSetAttribute(r_kernel,      cudaFuncAttributeMaxDynamicSharedMemorySize, R_SMEM);
    cudaFuncSetAttribute(zp_kernel,     cudaFuncAttributeMaxDynamicSharedMemorySize, ZP_SMEM);

    proj_kernel<<<dim3(40, 4), 256>>>(x, Wkk, bkk);
    wq_kernel<<<dim3(64, 4, NH), 256>>>(WKq);
    aqattn_kernel<<<dim3(4, TT, NH), 256, AQ_SMEM>>>();
    t1_kernel<<<dim3(2, TT, NH), 256, T1_SMEM>>>();
    r_kernel<<<dim3(128, NH), 256, R_SMEM>>>();
    zp_kernel<<<dim3(NSPLIT, 4, NH), 256, ZP_SMEM>>>(WVq);
    zred_kernel<<<512, 256>>>();
    out_kernel<<<dim3(8, 4), 256>>>(Wout, bout, out);
}

// round 11
// speedup vs baseline: 1.2961x; 1.2961x over previous
#include <cuda_runtime.h>
#include <cstdint>

#define NH 8
#define TT 256
#define DHD 64
#define DD 512
#define NSPLIT 8

// ---------------- scratch (static __device__, allocation-free) ----------------
__device__ float g_heads[5][NH][TT][DHD];          // k1,k2,q,v1,v2
__device__ float g_Wq[NH][TT][DHD * DHD];          // [h][q][k*64+j]
__device__ float g_S[NH][TT][TT][TT];              // [h][q][p][t]
__device__ float g_T1[NH][TT][TT][DHD];            // [h][q][p][c]
__device__ float g_R[NH][TT][DHD * DHD];           // [h][q][a*64+c]
__device__ float g_pmax[NH][TT][4];                // per-64-stripe max of S
__device__ float g_psum[NH][TT][4];                // per-64-stripe sum of exp
__device__ float g_zp[NSPLIT][NH][4][64][64];      // z split-K partials
__device__ float g_z[TT][DD];                      // attention output

// ============================ TF32 MMA (K-path) ===============================
__device__ __forceinline__ float to_tf32(float x) {
    uint32_t u; asm("cvt.rna.tf32.f32 %0, %1;" : "=r"(u) : "f"(x));
    return __uint_as_float(u);
}
__device__ __forceinline__ void mma8(float* c, float a0, float a1, float a2, float a3,
                                     float b0, float b1) {
    asm volatile(
        "mma.sync.aligned.m16n8k8.row.col.f32.tf32.tf32.f32 "
        "{%0,%1,%2,%3},{%4,%5,%6,%7},{%8,%9},{%0,%1,%2,%3};"
        : "+f"(c[0]), "+f"(c[1]), "+f"(c[2]), "+f"(c[3])
        : "r"(__float_as_uint(a0)), "r"(__float_as_uint(a1)),
          "r"(__float_as_uint(a2)), "r"(__float_as_uint(a3)),
          "r"(__float_as_uint(b0)), "r"(__float_as_uint(b1)));
}
// 16x32 warp tile, As[m][k] pad 68, Bs[k][n] pad 72
__device__ __forceinline__ void wtile(const float (*As)[68], const float (*Bs)[72],
                                      float acc[4][4], int m0, int n0, int gid, int tig) {
#pragma unroll
    for (int kc = 0; kc < 64; kc += 8) {
        float a0 = As[m0 + gid][kc + tig],     a1 = As[m0 + gid + 8][kc + tig];
        float a2 = As[m0 + gid][kc + tig + 4], a3 = As[m0 + gid + 8][kc + tig + 4];
#pragma unroll
        for (int nt = 0; nt < 4; nt++) {
            int n = n0 + nt * 8;
            mma8(acc[nt], a0, a1, a2, a3, Bs[kc + tig][n + gid], Bs[kc + tig + 4][n + gid]);
        }
    }
}
// gmem [m][k] -> As[m][k] (tf32)
__device__ __forceinline__ void ldA(const float* __restrict__ src, int lda,
                                    float (*As)[68], int tid) {
#pragma unroll
    for (int i = 0; i < 4; i++) {
        int id = tid + i * 256, r = id >> 4, c = (id & 15) << 2;
        float4 v = *reinterpret_cast<const float4*>(src + (long)r * lda + c);
        float4 w = {to_tf32(v.x), to_tf32(v.y), to_tf32(v.z), to_tf32(v.w)};
        *reinterpret_cast<float4*>(&As[r][c]) = w;
    }
}
// gmem [k][n] -> Bs[k][n] (tf32)
__device__ __forceinline__ void ldB(const float* __restrict__ src, int ldb,
                                    float (*Bs)[72], int tid) {
#pragma unroll
    for (int i = 0; i < 4; i++) {
        int id = tid + i * 256, r = id >> 4, c = (id & 15) << 2;
        float4 v = *reinterpret_cast<const float4*>(src + (long)r * ldb + c);
        float4 w = {to_tf32(v.x), to_tf32(v.y), to_tf32(v.z), to_tf32(v.w)};
        *reinterpret_cast<float4*>(&Bs[r][c]) = w;
    }
}
// gmem [n][k] -> Bs[k][n] (tf32)
__device__ __forceinline__ void ldBt(const float* __restrict__ src, int ldbt,
                                     float (*Bs)[72], int tid) {
#pragma unroll
    for (int i = 0; i < 4; i++) {
        int id = tid + i * 256, n = id & 63, kb = (id >> 6) << 2;
        float4 v = *reinterpret_cast<const float4*>(src + (long)n * ldbt + kb);
        Bs[kb][n] = to_tf32(v.x); Bs[kb + 1][n] = to_tf32(v.y);
        Bs[kb + 2][n] = to_tf32(v.z); Bs[kb + 3][n] = to_tf32(v.w);
    }
}
// 16x32 store
__device__ __forceinline__ void store_tile(float* C, int ldc, const float acc[4][4],
                                           int m0, int n0, int gid, int tig) {
#pragma unroll
    for (int nt = 0; nt < 4; nt++) {
        int n = n0 + nt * 8 + 2 * tig;
        *reinterpret_cast<float2*>(C + (long)(m0 + gid) * ldc + n) =
            make_float2(acc[nt][0], acc[nt][1]);
        *reinterpret_cast<float2*>(C + (long)(m0 + gid + 8) * ldc + n) =
            make_float2(acc[nt][2], acc[nt][3]);
    }
}

// ============================ BF16x3 MMA (V-path) =============================
// pack {lo16: x0, hi16: x1}; element order: x0 = even k, x1 = odd k
__device__ __forceinline__ uint32_t pack2(float x0, float x1) {
    uint32_t d;
    asm("cvt.rn.bf16x2.f32 %0, %1, %2;" : "=r"(d) : "f"(x1), "f"(x0));
    return d;
}
__device__ __forceinline__ void split_pack(float x0, float x1, uint32_t& h, uint32_t& l) {
    h = pack2(x0, x1);
    float h0 = __uint_as_float((h & 0xFFFFu) << 16);
    float h1 = __uint_as_float(h & 0xFFFF0000u);
    l = pack2(x0 - h0, x1 - h1);
}
__device__ __forceinline__ void mmabf(float* c, uint32_t a0, uint32_t a1, uint32_t a2,
                                      uint32_t a3, uint32_t b0, uint32_t b1) {
    asm volatile(
        "mma.sync.aligned.m16n8k16.row.col.f32.bf16.bf16.f32 "
        "{%0,%1,%2,%3},{%4,%5,%6,%7},{%8,%9},{%0,%1,%2,%3};"
        : "+f"(c[0]), "+f"(c[1]), "+f"(c[2]), "+f"(c[3])
        : "r"(a0), "r"(a1), "r"(a2), "r"(a3), "r"(b0), "r"(b1));
}
// 16x32 warp tile, 3-term bf16. A2[m][kpair] pad 36, B2[kpair][n] pad BP. K=64.
template<int BP>
__device__ __forceinline__ void wtbf3(const uint32_t (*Ah)[36], const uint32_t (*Al)[36],
                                      const uint32_t (*Bh)[BP], const uint32_t (*Bl)[BP],
                                      float acc[4][4], int m0, int n0, int gid, int tig) {
#pragma unroll
    for (int s = 0; s < 4; s++) {          // four k16 chunks
        int kb = s * 8;
        uint32_t ah0 = Ah[m0 + gid][kb + tig],     ah1 = Ah[m0 + gid + 8][kb + tig];
        uint32_t ah2 = Ah[m0 + gid][kb + tig + 4], ah3 = Ah[m0 + gid + 8][kb + tig + 4];
        uint32_t al0 = Al[m0 + gid][kb + tig],     al1 = Al[m0 + gid + 8][kb + tig];
        uint32_t al2 = Al[m0 + gid][kb + tig + 4], al3 = Al[m0 + gid + 8][kb + tig + 4];
#pragma unroll
        for (int nt = 0; nt < 4; nt++) {
            int n = n0 + nt * 8;
            uint32_t bh0 = Bh[kb + tig][n + gid], bh1 = Bh[kb + tig + 4][n + gid];
            uint32_t bl0 = Bl[kb + tig][n + gid], bl1 = Bl[kb + tig + 4][n + gid];
            mmabf(acc[nt], ah0, ah1, ah2, ah3, bh0, bh1);
            mmabf(acc[nt], al0, al1, al2, al3, bh0, bh1);
            mmabf(acc[nt], ah0, ah1, ah2, ah3, bl0, bl1);
        }
    }
}
// gmem [m][k] (k contiguous) -> A2[m][kpair] split (64x64 floats)
__device__ __forceinline__ void ldbfA(const float* __restrict__ src, int lda,
                                      uint32_t (*Ah)[36], uint32_t (*Al)[36], int tid) {
#pragma unroll
    for (int i = 0; i < 2; i++) {
        int id = tid + i * 256, r = id >> 3, c8 = (id & 7) << 3;
        const float* p = src + (long)r * lda + c8;
        float4 v0 = *reinterpret_cast<const float4*>(p);
        float4 v1 = *reinterpret_cast<const float4*>(p + 4);
        uint32_t h[4], l[4];
        split_pack(v0.x, v0.y, h[0], l[0]); split_pack(v0.z, v0.w, h[1], l[1]);
        split_pack(v1.x, v1.y, h[2], l[2]); split_pack(v1.z, v1.w, h[3], l[3]);
        *reinterpret_cast<uint4*>(&Ah[r][c8 >> 1]) = make_uint4(h[0], h[1], h[2], h[3]);
        *reinterpret_cast<uint4*>(&Al[r][c8 >> 1]) = make_uint4(l[0], l[1], l[2], l[3]);
    }
}
// gmem [k][n] (n contiguous, 64 wide) -> B2[kpair][n] split (row-pair pack)
__device__ __forceinline__ void ldbfB(const float* __restrict__ src, int ldb,
                                      uint32_t (*Bh)[72], uint32_t (*Bl)[72], int tid) {
#pragma unroll
    for (int i = 0; i < 2; i++) {
        int id = tid + i * 256, tp = id >> 4, c4 = (id & 15) << 2;
        const float* p0 = src + (long)(2 * tp) * ldb + c4;
        const float* p1 = p0 + ldb;
        float4 a = *reinterpret_cast<const float4*>(p0);
        float4 b = *reinterpret_cast<const float4*>(p1);
        uint32_t h[4], l[4];
        split_pack(a.x, b.x, h[0], l[0]); split_pack(a.y, b.y, h[1], l[1]);
        split_pack(a.z, b.z, h[2], l[2]); split_pack(a.w, b.w, h[3], l[3]);
        *reinterpret_cast<uint4*>(&Bh[tp][c4]) = make_uint4(h[0], h[1], h[2], h[3]);
        *reinterpret_cast<uint4*>(&Bl[tp][c4]) = make_uint4(l[0], l[1], l[2], l[3]);
    }
}
// gmem [k][m] (m contiguous) -> A2[m][kpair] split (transposed pack, 64x64)
__device__ __forceinline__ void ldbfAt(const float* __restrict__ src, int ldx,
                                       uint32_t (*Ah)[36], uint32_t (*Al)[36], int tid) {
#pragma unroll
    for (int i = 0; i < 2; i++) {
        int id = tid + i * 256, pp = id & 31, a4 = (id >> 5) << 2;
        const float* p0 = src + (long)(2 * pp) * ldx + a4;
        const float* p1 = p0 + ldx;
        float4 a = *reinterpret_cast<const float4*>(p0);
        float4 b = *reinterpret_cast<const float4*>(p1);
        uint32_t h, l;
        split_pack(a.x, b.x, h, l); Ah[a4][pp] = h;     Al[a4][pp] = l;
        split_pack(a.y, b.y, h, l); Ah[a4 + 1][pp] = h; Al[a4 + 1][pp] = l;
        split_pack(a.z, b.z, h, l); Ah[a4 + 2][pp] = h; Al[a4 + 2][pp] = l;
        split_pack(a.w, b.w, h, l); Ah[a4 + 3][pp] = h; Al[a4 + 3][pp] = l;
    }
}

// bf16 split kernels share one smem layout (uint32 offsets); 36864 B total
#define BF_AH 0
#define BF_AL (64 * 36)
#define BF_BH (2 * 64 * 36)
#define BF_BL (2 * 64 * 36 + 32 * 72)
#define BF_SMEM ((2 * 64 * 36 + 2 * 32 * 72) * 4)

// ===================== FFMA 64x64 tile (proj/out only) ========================
__device__ __forceinline__ void f_loadAT(const float* __restrict__ A, int lda,
                                         float As[64][68], int tid) {
#pragma unroll
    for (int i = 0; i < 4; i++) {
        int id = tid + i * 256, r = id >> 4, c = (id & 15) << 2;
        float4 v = *reinterpret_cast<const float4*>(A + (long)r * lda + c);
        As[c][r] = v.x; As[c + 1][r] = v.y; As[c + 2][r] = v.z; As[c + 3][r] = v.w;
    }
}
__device__ __forceinline__ void f_loadB(const float* __restrict__ B, int ldb,
                                        float Bs[64][68], int tid) {
#pragma unroll
    for (int i = 0; i < 4; i++) {
        int id = tid + i * 256, r = id >> 4, c = (id & 15) << 2;
        float4 v = *reinterpret_cast<const float4*>(B + (long)r * ldb + c);
        *reinterpret_cast<float4*>(&Bs[r][c]) = v;
    }
}
__device__ __forceinline__ void f_mma(const float As[64][68], const float Bs[64][68],
                                      float acc[4][4], int tm, int tn) {
#pragma unroll
    for (int k = 0; k < 64; k++) {
        float4 a = *reinterpret_cast<const float4*>(&As[k][tm * 4]);
        float4 b = *reinterpret_cast<const float4*>(&Bs[k][tn * 4]);
        acc[0][0] += a.x * b.x; acc[0][1] += a.x * b.y; acc[0][2] += a.x * b.z; acc[0][3] += a.x * b.w;
        acc[1][0] += a.y * b.x; acc[1][1] += a.y * b.y; acc[1][2] += a.y * b.z; acc[1][3] += a.y * b.w;
        acc[2][0] += a.z * b.x; acc[2][1] += a.z * b.y; acc[2][2] += a.z * b.z; acc[2][3] += a.z * b.w;
        acc[3][0] += a.w * b.x; acc[3][1] += a.w * b.y; acc[3][2] += a.w * b.z; acc[3][3] += a.w * b.w;
    }
}

// ---------------- K0: proj = x @ W_kkqvv + b (fp32 FFMA), scatter -------------
__global__ __launch_bounds__(256) void proj_kernel(const float* __restrict__ x,
                                                   const float* __restrict__ W,
                                                   const float* __restrict__ bias) {
    __shared__ float As[64][68];
    __shared__ float Bs[64][68];
    int tid = threadIdx.x, tm = tid >> 4, tn = tid & 15;
    int n0 = blockIdx.x * 64, m0 = blockIdx.y * 64;
    float acc[4][4] = {};
    for (int k0 = 0; k0 < DD; k0 += 64) {
        f_loadAT(x + (long)m0 * DD + k0, DD, As, tid);
        f_loadB(W + (long)k0 * (5 * DD) + n0, 5 * DD, Bs, tid);
        __syncthreads();
        f_mma(As, Bs, acc, tm, tn);
        __syncthreads();
    }
#pragma unroll
    for (int r = 0; r < 4; r++)
#pragma unroll
        for (int c = 0; c < 4; c++) {
            int row = m0 + tm * 4 + r;
            int col = n0 + tn * 4 + c;
            float v = acc[r][c] + bias[col];
            int part = col >> 9;
            int rem = col & 511;
            g_heads[part][rem >> 6][row][rem & 63] = v;
        }
}

// ---------------- K1: Wq = q @ W_Kq^T (tf32) ----------------------------------
__global__ __launch_bounds__(256) void wq_kernel(const float* __restrict__ WKq) {
    __shared__ float As[64][68];
    __shared__ float Bs[64][72];
    int tid = threadIdx.x, w = tid >> 5, lane = tid & 31;
    int gid = lane >> 2, tig = lane & 3;
    int m0 = (w & 3) * 16, n0 = (w >> 2) * 32;
    int kj0 = blockIdx.x * 64, q0 = blockIdx.y * 64, h = blockIdx.z;
    ldA(&g_heads[2][h][q0][0], 64, As, tid);                 // q [q][i]
    ldBt(WKq + ((long)h * 4096 + kj0) * 64, 64, Bs, tid);    // [kj][i] -> [i][kj]
    __syncthreads();
    float acc[4][4] = {};
    wtile(As, Bs, acc, m0, n0, gid, tig);
    store_tile(&g_Wq[h][q0][kj0], 4096, acc, m0, n0, gid, tig);
}

// ---- K2 (fused, tf32): Aq in smem, S over t-tiles, per-stripe max ------------
__global__ __launch_bounds__(256) void aqattn_kernel() {
    int pt = blockIdx.x, q = blockIdx.y, h = blockIdx.z;
    int qt = q >> 6;
    if (pt > qt) return;
    __shared__ float As[64][68];
    __shared__ float Bs[64][72];
    __shared__ float red[256];
    int tid = threadIdx.x, w = tid >> 5, lane = tid & 31;
    int gid = lane >> 2, tig = lane & 3;
    int m0 = (w & 3) * 16, n0 = (w >> 2) * 32;
    int p0 = pt << 6;

    ldA(&g_heads[0][h][p0][0], 64, As, tid);    // k1 [p][k]
    ldB(&g_Wq[h][q][0], 64, Bs, tid);           // Wq [k][j]
    __syncthreads();
    float accA[4][4] = {};
    wtile(As, Bs, accA, m0, n0, gid, tig);
    __syncthreads();
    // As := Aq[p][j] (tf32)
#pragma unroll
    for (int nt = 0; nt < 4; nt++) {
        int n = n0 + nt * 8 + 2 * tig;
        As[m0 + gid][n]     = to_tf32(accA[nt][0]);
        As[m0 + gid][n + 1] = to_tf32(accA[nt][1]);
        As[m0 + gid + 8][n]     = to_tf32(accA[nt][2]);
        As[m0 + gid + 8][n + 1] = to_tf32(accA[nt][3]);
    }
    __syncthreads();

    float vmax = -3.0e38f;
    float* C = &g_S[h][q][0][0];
    for (int tt = 0; tt <= qt; tt++) {
        ldBt(&g_heads[1][h][tt * 64][0], 64, Bs, tid);   // k2 [t][j] -> [j][t]
        __syncthreads();
        float acc[4][4] = {};
        wtile(As, Bs, acc, m0, n0, gid, tig);
#pragma unroll
        for (int nt = 0; nt < 4; nt++) {
            int n = n0 + nt * 8 + 2 * tig;
            int t = tt * 64 + n;
            int plo = p0 + m0 + gid, phi = plo + 8;
            float v00 = (plo > q || t > q)     ? -1e30f : acc[nt][0] * (1.0f / 64.0f);
            float v01 = (plo > q || t + 1 > q) ? -1e30f : acc[nt][1] * (1.0f / 64.0f);
            float v10 = (phi > q || t > q)     ? -1e30f : acc[nt][2] * (1.0f / 64.0f);
            float v11 = (phi > q || t + 1 > q) ? -1e30f : acc[nt][3] * (1.0f / 64.0f);
            *reinterpret_cast<float2*>(C + (long)plo * TT + t) = make_float2(v00, v01);
            *reinterpret_cast<float2*>(C + (long)phi * TT + t) = make_float2(v10, v11);
            vmax = fmaxf(vmax, fmaxf(fmaxf(v00, v01), fmaxf(v10, v11)));
        }
        __syncthreads();
    }
    red[tid] = vmax;
    __syncthreads();
    for (int off = 128; off > 0; off >>= 1) {
        if (tid < off) red[tid] = fmaxf(red[tid], red[tid + off]);
        __syncthreads();
    }
    if (tid == 0) g_pmax[h][q][pt] = red[0];
}

// ---- K3 (fused softmax + PV step 1, bf16x3): T1 = exp(S-M) @ v2 --------------
__global__ __launch_bounds__(256) void t1_kernel() {
    int pt = blockIdx.x, q = blockIdx.y, h = blockIdx.z;
    int qt = q >> 6;
    if (pt > qt) return;
    extern __shared__ uint32_t smu[];
    uint32_t (*Ah)[36] = reinterpret_cast<uint32_t (*)[36]>(smu + BF_AH);
    uint32_t (*Al)[36] = reinterpret_cast<uint32_t (*)[36]>(smu + BF_AL);
    uint32_t (*Bh)[72] = reinterpret_cast<uint32_t (*)[72]>(smu + BF_BH);
    uint32_t (*Bl)[72] = reinterpret_cast<uint32_t (*)[72]>(smu + BF_BL);
    __shared__ float red[256];
    int tid = threadIdx.x, w = tid >> 5, lane = tid & 31;
    int gid = lane >> 2, tig = lane & 3;
    int m0 = (w & 3) * 16, n0 = (w >> 2) * 32;
    int p0 = pt << 6;

    float M = g_pmax[h][q][0];
    for (int pp = 1; pp <= qt; pp++) M = fmaxf(M, g_pmax[h][q][pp]);

    const float* Pm = &g_S[h][q][p0][0];        // [64 p][t], ld TT
    float lsum = 0.0f;
    float acc[4][4] = {};
    for (int ks = 0; ks <= qt; ks++) {
        // A := split(exp(S - M))  (masked entries are -1e30 -> exp -> 0)
#pragma unroll
        for (int i = 0; i < 2; i++) {
            int id = tid + i * 256, r = id >> 3, c8 = (id & 7) << 3;
            const float* p = Pm + (long)r * TT + ks * 64 + c8;
            float4 v0 = *reinterpret_cast<const float4*>(p);
            float4 v1 = *reinterpret_cast<const float4*>(p + 4);
            float e0 = __expf(v0.x - M), e1 = __expf(v0.y - M);
            float e2 = __expf(v0.z - M), e3 = __expf(v0.w - M);
            float e4 = __expf(v1.x - M), e5 = __expf(v1.y - M);
            float e6 = __expf(v1.z - M), e7 = __expf(v1.w - M);
            lsum += ((e0 + e1) + (e2 + e3)) + ((e4 + e5) + (e6 + e7));
            uint32_t hh[4], ll[4];
            split_pack(e0, e1, hh[0], ll[0]); split_pack(e2, e3, hh[1], ll[1]);
            split_pack(e4, e5, hh[2], ll[2]); split_pack(e6, e7, hh[3], ll[3]);
            *reinterpret_cast<uint4*>(&Ah[r][c8 >> 1]) = make_uint4(hh[0], hh[1], hh[2], hh[3]);
            *reinterpret_cast<uint4*>(&Al[r][c8 >> 1]) = make_uint4(ll[0], ll[1], ll[2], ll[3]);
        }
        ldbfB(&g_heads[4][h][ks * 64][0], 64, Bh, Bl, tid);    // v2 [t][c]
        __syncthreads();
        wtbf3<72>(Ah, Al, Bh, Bl, acc, m0, n0, gid, tig);
        __syncthreads();
    }
    store_tile(&g_T1[h][q][p0][0], 64, acc, m0, n0, gid, tig);
    red[tid] = lsum;
    __syncthreads();
    for (int off = 128; off > 0; off >>= 1) {
        if (tid < off) red[tid] += red[tid + off];
        __syncthreads();
    }
    if (tid == 0) g_psum[h][q][pt] = red[0];
}

// ---------------- K4 (bf16x3): R[a][c] = sum_p v1[p][a] * T1[p][c] ------------
__global__ __launch_bounds__(256) void r_kernel() {
    int q = blockIdx.x, h = blockIdx.y;
    int qt = q >> 6;
    extern __shared__ uint32_t smu[];
    uint32_t (*Ah)[36] = reinterpret_cast<uint32_t (*)[36]>(smu + BF_AH);
    uint32_t (*Al)[36] = reinterpret_cast<uint32_t (*)[36]>(smu + BF_AL);
    uint32_t (*Bh)[72] = reinterpret_cast<uint32_t (*)[72]>(smu + BF_BH);
    uint32_t (*Bl)[72] = reinterpret_cast<uint32_t (*)[72]>(smu + BF_BL);
    int tid = threadIdx.x, w = tid >> 5, lane = tid & 31;
    int gid = lane >> 2, tig = lane & 3;
    int m0 = (w & 3) * 16, n0 = (w >> 2) * 32;
    float acc[4][4] = {};
    for (int ks = 0; ks <= qt; ks++) {
        ldbfAt(&g_heads[3][h][ks * 64][0], 64, Ah, Al, tid);   // v1 [p][a] -> A2[a][ppair]
        ldbfB(&g_T1[h][q][ks * 64][0], 64, Bh, Bl, tid);       // T1 [p][c]
        __syncthreads();
        wtbf3<72>(Ah, Al, Bh, Bl, acc, m0, n0, gid, tig);
        __syncthreads();
    }
    store_tile(&g_R[h][q][0], 64, acc, m0, n0, gid, tig);
}

// ---------------- K5 (bf16x3): z_part = R @ W_Vq (split-K over ac) ------------
__global__ __launch_bounds__(256) void zp_kernel(const float* __restrict__ WVq) {
    extern __shared__ uint32_t smu[];
    uint32_t (*Ah)[36] = reinterpret_cast<uint32_t (*)[36]>(smu + BF_AH);
    uint32_t (*Al)[36] = reinterpret_cast<uint32_t (*)[36]>(smu + BF_AL);
    uint32_t (*Bh)[72] = reinterpret_cast<uint32_t (*)[72]>(smu + BF_BH);
    uint32_t (*Bl)[72] = reinterpret_cast<uint32_t (*)[72]>(smu + BF_BL);
    int tid = threadIdx.x, w = tid >> 5, lane = tid & 31;
    int gid = lane >> 2, tig = lane & 3;
    int m0 = (w & 3) * 16, n0 = (w >> 2) * 32;
    int sp = blockIdx.x, qt = blockIdx.y, h = blockIdx.z;
    int q0 = qt << 6;
    int ac0 = sp * (4096 / NSPLIT);
    float acc[4][4] = {};
    for (int ks = 0; ks < 4096 / NSPLIT / 64; ks++) {
        ldbfA(&g_R[h][q0][0] + ac0 + ks * 64, 4096, Ah, Al, tid);
        ldbfB(WVq + ((long)h * 4096 + ac0 + ks * 64) * 64, 64, Bh, Bl, tid);
        __syncthreads();
        wtbf3<72>(Ah, Al, Bh, Bl, acc, m0, n0, gid, tig);
        __syncthreads();
    }
    store_tile(&g_zp[sp][h][qt][0][0], 64, acc, m0, n0, gid, tig);
}

// ---------------- K6: reduce split-K, divide by rowsum ------------------------
__global__ __launch_bounds__(256) void zred_kernel() {
    int idx = blockIdx.x * 256 + threadIdx.x;  // 256*512
    int q = idx >> 9, col = idx & 511;
    int h = col >> 6;
    int qt = q >> 6, ql = q & 63;
    int e = col & 63;
    float s = 0.0f;
#pragma unroll
    for (int sp = 0; sp < NSPLIT; sp++) s += g_zp[sp][h][qt][ql][e];
    float rs = 0.0f;
    for (int pp = 0; pp <= qt; pp++) rs += g_psum[h][q][pp];
    g_z[q][col] = s / rs;
}

// ---------------- K7: out = z @ W_out + b_out (fp32 FFMA) ---------------------
__global__ __launch_bounds__(256) void out_kernel(const float* __restrict__ Wout,
                                                  const float* __restrict__ bout,
                                                  float* __restrict__ out) {
    __shared__ float As[64][68];
    __shared__ float Bs[64][68];
    int tid = threadIdx.x, tm = tid >> 4, tn = tid & 15;
    int n0 = blockIdx.x * 64, m0 = blockIdx.y * 64;
    float acc[4][4] = {};
    for (int k0 = 0; k0 < DD; k0 += 64) {
        f_loadAT(&g_z[m0][k0], DD, As, tid);
        f_loadB(Wout + (long)k0 * DD + n0, DD, Bs, tid);
        __syncthreads();
        f_mma(As, Bs, acc, tm, tn);
        __syncthreads();
    }
#pragma unroll
    for (int r = 0; r < 4; r++)
#pragma unroll
        for (int c = 0; c < 4; c++) {
            int row = m0 + tm * 4 + r;
            int col = n0 + tn * 4 + c;
            out[(long)row * DD + col] = acc[r][c] + bout[col];
        }
}

// ---------------- launch ------------------------------------------------------
extern "C" void kernel_launch(void* const* d_in, const int* in_sizes, int n_in,
                              void* d_out, int out_size) {
    const float* x    = (const float*)d_in[0];
    const float* Wkk  = (const float*)d_in[1];
    const float* bkk  = (const float*)d_in[2];
    const float* WKq  = (const float*)d_in[3];
    const float* WVq  = (const float*)d_in[4];
    const float* Wout = (const float*)d_in[5];
    const float* bout = (const float*)d_in[6];
    float* out = (float*)d_out;

    cudaFuncSetAttribute(t1_kernel, cudaFuncAttributeMaxDynamicSharedMemorySize, BF_SMEM);
    cudaFuncSetAttribute(r_kernel,  cudaFuncAttributeMaxDynamicSharedMemorySize, BF_SMEM);
    cudaFuncSetAttribute(zp_kernel, cudaFuncAttributeMaxDynamicSharedMemorySize, BF_SMEM);

    proj_kernel<<<dim3(40, 4), 256>>>(x, Wkk, bkk);
    wq_kernel<<<dim3(64, 4, NH), 256>>>(WKq);
    aqattn_kernel<<<dim3(4, TT, NH), 256>>>();
    t1_kernel<<<dim3(4, TT, NH), 256, BF_SMEM>>>();
    r_kernel<<<dim3(TT, NH), 256, BF_SMEM>>>();
    zp_kernel<<<dim3(NSPLIT, 4, NH), 256, BF_SMEM>>>(WVq);
    zred_kernel<<<512, 256>>>();
    out_kernel<<<dim3(8, 4), 256>>>(Wout, bout, out);
}

// round 17
// speedup vs baseline: 1.4443x; 1.1144x over previous
#include <cuda_runtime.h>
#include <cstdint>

#define NH 8
#define TT 256
#define DHD 64
#define DD 512
#define NSPLIT 8

// ---------------- scratch (static __device__, allocation-free) ----------------
__device__ float g_heads[5][NH][TT][DHD];          // k1,k2,q,v1,v2
__device__ float g_Wq[NH][TT][DHD * DHD];          // [h][q][k*64+j]
__device__ float g_T1[NH][TT][TT][DHD];            // [h][q][p][c] (stripe-scaled)
__device__ float g_R[NH][TT][DHD * DHD];           // [h][q][a*64+c]
__device__ float g_pmax[NH][TT][4];                // per-64-stripe running max
__device__ float g_psum[NH][TT][4];                // per-64-stripe sum of exp(S-Mb)
__device__ float g_zp[NSPLIT][NH][4][64][64];      // z split-K partials
__device__ float g_z[TT][DD];                      // attention output

// ============================ TF32 MMA (K-path) ===============================
__device__ __forceinline__ float to_tf32(float x) {
    uint32_t u; asm("cvt.rna.tf32.f32 %0, %1;" : "=r"(u) : "f"(x));
    return __uint_as_float(u);
}
__device__ __forceinline__ void mma8(float* c, float a0, float a1, float a2, float a3,
                                     float b0, float b1) {
    asm volatile(
        "mma.sync.aligned.m16n8k8.row.col.f32.tf32.tf32.f32 "
        "{%0,%1,%2,%3},{%4,%5,%6,%7},{%8,%9},{%0,%1,%2,%3};"
        : "+f"(c[0]), "+f"(c[1]), "+f"(c[2]), "+f"(c[3])
        : "r"(__float_as_uint(a0)), "r"(__float_as_uint(a1)),
          "r"(__float_as_uint(a2)), "r"(__float_as_uint(a3)),
          "r"(__float_as_uint(b0)), "r"(__float_as_uint(b1)));
}
// 16x32 warp tile, As[m][k] pad 68, Bs[k][n] pad 72
__device__ __forceinline__ void wtile(const float (*As)[68], const float (*Bs)[72],
                                      float acc[4][4], int m0, int n0, int gid, int tig) {
#pragma unroll
    for (int kc = 0; kc < 64; kc += 8) {
        float a0 = As[m0 + gid][kc + tig],     a1 = As[m0 + gid + 8][kc + tig];
        float a2 = As[m0 + gid][kc + tig + 4], a3 = As[m0 + gid + 8][kc + tig + 4];
#pragma unroll
        for (int nt = 0; nt < 4; nt++) {
            int n = n0 + nt * 8;
            mma8(acc[nt], a0, a1, a2, a3, Bs[kc + tig][n + gid], Bs[kc + tig + 4][n + gid]);
        }
    }
}
// gmem [m][k] -> As[m][k] (tf32)
__device__ __forceinline__ void ldA(const float* __restrict__ src, int lda,
                                    float (*As)[68], int tid) {
#pragma unroll
    for (int i = 0; i < 4; i++) {
        int id = tid + i * 256, r = id >> 4, c = (id & 15) << 2;
        float4 v = *reinterpret_cast<const float4*>(src + (long)r * lda + c);
        float4 w = {to_tf32(v.x), to_tf32(v.y), to_tf32(v.z), to_tf32(v.w)};
        *reinterpret_cast<float4*>(&As[r][c]) = w;
    }
}
// gmem [k][n] -> Bs[k][n] (tf32)
__device__ __forceinline__ void ldB(const float* __restrict__ src, int ldb,
                                    float (*Bs)[72], int tid) {
#pragma unroll
    for (int i = 0; i < 4; i++) {
        int id = tid + i * 256, r = id >> 4, c = (id & 15) << 2;
        float4 v = *reinterpret_cast<const float4*>(src + (long)r * ldb + c);
        float4 w = {to_tf32(v.x), to_tf32(v.y), to_tf32(v.z), to_tf32(v.w)};
        *reinterpret_cast<float4*>(&Bs[r][c]) = w;
    }
}
// gmem [n][k] -> Bs[k][n] (tf32)
__device__ __forceinline__ void ldBt(const float* __restrict__ src, int ldbt,
                                     float (*Bs)[72], int tid) {
#pragma unroll
    for (int i = 0; i < 4; i++) {
        int id = tid + i * 256, n = id & 63, kb = (id >> 6) << 2;
        float4 v = *reinterpret_cast<const float4*>(src + (long)n * ldbt + kb);
        Bs[kb][n] = to_tf32(v.x); Bs[kb + 1][n] = to_tf32(v.y);
        Bs[kb + 2][n] = to_tf32(v.z); Bs[kb + 3][n] = to_tf32(v.w);
    }
}
// 16x32 store
__device__ __forceinline__ void store_tile(float* C, int ldc, const float acc[4][4],
                                           int m0, int n0, int gid, int tig) {
#pragma unroll
    for (int nt = 0; nt < 4; nt++) {
        int n = n0 + nt * 8 + 2 * tig;
        *reinterpret_cast<float2*>(C + (long)(m0 + gid) * ldc + n) =
            make_float2(acc[nt][0], acc[nt][1]);
        *reinterpret_cast<float2*>(C + (long)(m0 + gid + 8) * ldc + n) =
            make_float2(acc[nt][2], acc[nt][3]);
    }
}

// ============================ BF16x3 MMA (V-path) =============================
__device__ __forceinline__ uint32_t pack2(float x0, float x1) {
    uint32_t d;
    asm("cvt.rn.bf16x2.f32 %0, %1, %2;" : "=r"(d) : "f"(x1), "f"(x0));
    return d;
}
__device__ __forceinline__ void split_pack(float x0, float x1, uint32_t& h, uint32_t& l) {
    h = pack2(x0, x1);
    float h0 = __uint_as_float((h & 0xFFFFu) << 16);
    float h1 = __uint_as_float(h & 0xFFFF0000u);
    l = pack2(x0 - h0, x1 - h1);
}
__device__ __forceinline__ void mmabf(float* c, uint32_t a0, uint32_t a1, uint32_t a2,
                                      uint32_t a3, uint32_t b0, uint32_t b1) {
    asm volatile(
        "mma.sync.aligned.m16n8k16.row.col.f32.bf16.bf16.f32 "
        "{%0,%1,%2,%3},{%4,%5,%6,%7},{%8,%9},{%0,%1,%2,%3};"
        : "+f"(c[0]), "+f"(c[1]), "+f"(c[2]), "+f"(c[3])
        : "r"(a0), "r"(a1), "r"(a2), "r"(a3), "r"(b0), "r"(b1));
}
// 16x32 warp tile, 3-term bf16. A2[m][kpair] pad 36, B2[kpair][n] pad BP. K=64.
template<int BP>
__device__ __forceinline__ void wtbf3(const uint32_t (*Ah)[36], const uint32_t (*Al)[36],
                                      const uint32_t (*Bh)[BP], const uint32_t (*Bl)[BP],
                                      float acc[4][4], int m0, int n0, int gid, int tig) {
#pragma unroll
    for (int s = 0; s < 4; s++) {
        int kb = s * 8;
        uint32_t ah0 = Ah[m0 + gid][kb + tig],     ah1 = Ah[m0 + gid + 8][kb + tig];
        uint32_t ah2 = Ah[m0 + gid][kb + tig + 4], ah3 = Ah[m0 + gid + 8][kb + tig + 4];
        uint32_t al0 = Al[m0 + gid][kb + tig],     al1 = Al[m0 + gid + 8][kb + tig];
        uint32_t al2 = Al[m0 + gid][kb + tig + 4], al3 = Al[m0 + gid + 8][kb + tig + 4];
#pragma unroll
        for (int nt = 0; nt < 4; nt++) {
            int n = n0 + nt * 8;
            uint32_t bh0 = Bh[kb + tig][n + gid], bh1 = Bh[kb + tig + 4][n + gid];
            uint32_t bl0 = Bl[kb + tig][n + gid], bl1 = Bl[kb + tig + 4][n + gid];
            mmabf(acc[nt], ah0, ah1, ah2, ah3, bh0, bh1);
            mmabf(acc[nt], al0, al1, al2, al3, bh0, bh1);
            mmabf(acc[nt], ah0, ah1, ah2, ah3, bl0, bl1);
        }
    }
}
// gmem [m][k] (k contiguous) -> A2[m][kpair] split
__device__ __forceinline__ void ldbfA(const float* __restrict__ src, int lda,
                                      uint32_t (*Ah)[36], uint32_t (*Al)[36], int tid) {
#pragma unroll
    for (int i = 0; i < 2; i++) {
        int id = tid + i * 256, r = id >> 3, c8 = (id & 7) << 3;
        const float* p = src + (long)r * lda + c8;
        float4 v0 = *reinterpret_cast<const float4*>(p);
        float4 v1 = *reinterpret_cast<const float4*>(p + 4);
        uint32_t h[4], l[4];
        split_pack(v0.x, v0.y, h[0], l[0]); split_pack(v0.z, v0.w, h[1], l[1]);
        split_pack(v1.x, v1.y, h[2], l[2]); split_pack(v1.z, v1.w, h[3], l[3]);
        *reinterpret_cast<uint4*>(&Ah[r][c8 >> 1]) = make_uint4(h[0], h[1], h[2], h[3]);
        *reinterpret_cast<uint4*>(&Al[r][c8 >> 1]) = make_uint4(l[0], l[1], l[2], l[3]);
    }
}
// gmem [k][n] (n contiguous, 64 wide) -> B2[kpair][n] split (row-pair pack)
__device__ __forceinline__ void ldbfB(const float* __restrict__ src, int ldb,
                                      uint32_t (*Bh)[72], uint32_t (*Bl)[72], int tid) {
#pragma unroll
    for (int i = 0; i < 2; i++) {
        int id = tid + i * 256, tp = id >> 4, c4 = (id & 15) << 2;
        const float* p0 = src + (long)(2 * tp) * ldb + c4;
        const float* p1 = p0 + ldb;
        float4 a = *reinterpret_cast<const float4*>(p0);
        float4 b = *reinterpret_cast<const float4*>(p1);
        uint32_t h[4], l[4];
        split_pack(a.x, b.x, h[0], l[0]); split_pack(a.y, b.y, h[1], l[1]);
        split_pack(a.z, b.z, h[2], l[2]); split_pack(a.w, b.w, h[3], l[3]);
        *reinterpret_cast<uint4*>(&Bh[tp][c4]) = make_uint4(h[0], h[1], h[2], h[3]);
        *reinterpret_cast<uint4*>(&Bl[tp][c4]) = make_uint4(l[0], l[1], l[2], l[3]);
    }
}
// same, with uniform scale applied before split (for stripe rescale in r_kernel)
__device__ __forceinline__ void ldbfB_s(const float* __restrict__ src, int ldb, float s,
                                        uint32_t (*Bh)[72], uint32_t (*Bl)[72], int tid) {
#pragma unroll
    for (int i = 0; i < 2; i++) {
        int id = tid + i * 256, tp = id >> 4, c4 = (id & 15) << 2;
        const float* p0 = src + (long)(2 * tp) * ldb + c4;
        const float* p1 = p0 + ldb;
        float4 a = *reinterpret_cast<const float4*>(p0);
        float4 b = *reinterpret_cast<const float4*>(p1);
        uint32_t h[4], l[4];
        split_pack(a.x * s, b.x * s, h[0], l[0]); split_pack(a.y * s, b.y * s, h[1], l[1]);
        split_pack(a.z * s, b.z * s, h[2], l[2]); split_pack(a.w * s, b.w * s, h[3], l[3]);
        *reinterpret_cast<uint4*>(&Bh[tp][c4]) = make_uint4(h[0], h[1], h[2], h[3]);
        *reinterpret_cast<uint4*>(&Bl[tp][c4]) = make_uint4(l[0], l[1], l[2], l[3]);
    }
}
// gmem [k][m] (m contiguous) -> A2[m][kpair] split (transposed pack, 64x64)
__device__ __forceinline__ void ldbfAt(const float* __restrict__ src, int ldx,
                                       uint32_t (*Ah)[36], uint32_t (*Al)[36], int tid) {
#pragma unroll
    for (int i = 0; i < 2; i++) {
        int id = tid + i * 256, pp = id & 31, a4 = (id >> 5) << 2;
        const float* p0 = src + (long)(2 * pp) * ldx + a4;
        const float* p1 = p0 + ldx;
        float4 a = *reinterpret_cast<const float4*>(p0);
        float4 b = *reinterpret_cast<const float4*>(p1);
        uint32_t h, l;
        split_pack(a.x, b.x, h, l); Ah[a4][pp] = h;     Al[a4][pp] = l;
        split_pack(a.y, b.y, h, l); Ah[a4 + 1][pp] = h; Al[a4 + 1][pp] = l;
        split_pack(a.z, b.z, h, l); Ah[a4 + 2][pp] = h; Al[a4 + 2][pp] = l;
        split_pack(a.w, b.w, h, l); Ah[a4 + 3][pp] = h; Al[a4 + 3][pp] = l;
    }
}

// bf16 split kernels (r, zp) smem layout (uint32 offsets); 36864 B total
#define BF_AH 0
#define BF_AL (64 * 36)
#define BF_BH (2 * 64 * 36)
#define BF_BL (2 * 64 * 36 + 32 * 72)
#define BF_SMEM ((2 * 64 * 36 + 2 * 32 * 72) * 4)

// fused attn kernel smem layout (float offsets); 54272 B total
// AqS f32[64][68] | UNION( Bs f32[64][72] | Bh,Bl u32[32][72] ) | ( Atmp f32[64][68] | Ah,Al u32[64][36] )
#define FU_AQS 0
#define FU_UN  (64 * 68)
#define FU_AT  (64 * 68 + 64 * 72)
#define FU_SMEM ((64 * 68 + 64 * 72 + 2 * 64 * 36) * 4)

// ===================== FFMA 64x64 tile (proj/out only) ========================
__device__ __forceinline__ void f_loadAT(const float* __restrict__ A, int lda,
                                         float As[64][68], int tid) {
#pragma unroll
    for (int i = 0; i < 4; i++) {
        int id = tid + i * 256, r = id >> 4, c = (id & 15) << 2;
        float4 v = *reinterpret_cast<const float4*>(A + (long)r * lda + c);
        As[c][r] = v.x; As[c + 1][r] = v.y; As[c + 2][r] = v.z; As[c + 3][r] = v.w;
    }
}
__device__ __forceinline__ void f_loadB(const float* __restrict__ B, int ldb,
                                        float Bs[64][68], int tid) {
#pragma unroll
    for (int i = 0; i < 4; i++) {
        int id = tid + i * 256, r = id >> 4, c = (id & 15) << 2;
        float4 v = *reinterpret_cast<const float4*>(B + (long)r * ldb + c);
        *reinterpret_cast<float4*>(&Bs[r][c]) = v;
    }
}
__device__ __forceinline__ void f_mma(const float As[64][68], const float Bs[64][68],
                                      float acc[4][4], int tm, int tn) {
#pragma unroll
    for (int k = 0; k < 64; k++) {
        float4 a = *reinterpret_cast<const float4*>(&As[k][tm * 4]);
        float4 b = *reinterpret_cast<const float4*>(&Bs[k][tn * 4]);
        acc[0][0] += a.x * b.x; acc[0][1] += a.x * b.y; acc[0][2] += a.x * b.z; acc[0][3] += a.x * b.w;
        acc[1][0] += a.y * b.x; acc[1][1] += a.y * b.y; acc[1][2] += a.y * b.z; acc[1][3] += a.y * b.w;
        acc[2][0] += a.z * b.x; acc[2][1] += a.z * b.y; acc[2][2] += a.z * b.z; acc[2][3] += a.z * b.w;
        acc[3][0] += a.w * b.x; acc[3][1] += a.w * b.y; acc[3][2] += a.w * b.z; acc[3][3] += a.w * b.w;
    }
}

// ---------------- K0: proj = x @ W_kkqvv + b (fp32 FFMA), scatter -------------
__global__ __launch_bounds__(256) void proj_kernel(const float* __restrict__ x,
                                                   const float* __restrict__ W,
                                                   const float* __restrict__ bias) {
    __shared__ float As[64][68];
    __shared__ float Bs[64][68];
    int tid = threadIdx.x, tm = tid >> 4, tn = tid & 15;
    int n0 = blockIdx.x * 64, m0 = blockIdx.y * 64;
    float acc[4][4] = {};
    for (int k0 = 0; k0 < DD; k0 += 64) {
        f_loadAT(x + (long)m0 * DD + k0, DD, As, tid);
        f_loadB(W + (long)k0 * (5 * DD) + n0, 5 * DD, Bs, tid);
        __syncthreads();
        f_mma(As, Bs, acc, tm, tn);
        __syncthreads();
    }
#pragma unroll
    for (int r = 0; r < 4; r++)
#pragma unroll
        for (int c = 0; c < 4; c++) {
            int row = m0 + tm * 4 + r;
            int col = n0 + tn * 4 + c;
            float v = acc[r][c] + bias[col];
            int part = col >> 9;
            int rem = col & 511;
            g_heads[part][rem >> 6][row][rem & 63] = v;
        }
}

// ---------------- K1: Wq = q @ W_Kq^T (tf32) ----------------------------------
__global__ __launch_bounds__(256) void wq_kernel(const float* __restrict__ WKq) {
    __shared__ float As[64][68];
    __shared__ float Bs[64][72];
    int tid = threadIdx.x, w = tid >> 5, lane = tid & 31;
    int gid = lane >> 2, tig = lane & 3;
    int m0 = (w & 3) * 16, n0 = (w >> 2) * 32;
    int kj0 = blockIdx.x * 64, q0 = blockIdx.y * 64, h = blockIdx.z;
    ldA(&g_heads[2][h][q0][0], 64, As, tid);                 // q [q][i]
    ldBt(WKq + ((long)h * 4096 + kj0) * 64, 64, Bs, tid);    // [kj][i] -> [i][kj]
    __syncthreads();
    float acc[4][4] = {};
    wtile(As, Bs, acc, m0, n0, gid, tig);
    store_tile(&g_Wq[h][q0][kj0], 4096, acc, m0, n0, gid, tig);
}

// ==== K2 (FUSED flash): Aq -> S tiles in regs -> online exp -> T1 accum ======
// block (pt, q, h): T1[p0..p0+63][c] = sum_t exp(S[p][t]-Mb) v2[t][c], Mb running.
__global__ __launch_bounds__(256) void fused_attn_kernel() {
    int pt = blockIdx.x, q = blockIdx.y, h = blockIdx.z;
    int qt = q >> 6;
    if (pt > qt) return;
    extern __shared__ float sm[];
    float (*AqS)[68]   = reinterpret_cast<float (*)[68]>(sm + FU_AQS);
    float (*BsF)[72]   = reinterpret_cast<float (*)[72]>(sm + FU_UN);
    uint32_t (*Bh)[72] = reinterpret_cast<uint32_t (*)[72]>(sm + FU_UN);
    uint32_t (*Bl)[72] = reinterpret_cast<uint32_t (*)[72]>(sm + FU_UN + 32 * 72);
    float (*Atmp)[68]  = reinterpret_cast<float (*)[68]>(sm + FU_AT);
    uint32_t (*Ah)[36] = reinterpret_cast<uint32_t (*)[36]>(sm + FU_AT);
    uint32_t (*Al)[36] = reinterpret_cast<uint32_t (*)[36]>(sm + FU_AT + 64 * 36);
    __shared__ float red[8];
    int tid = threadIdx.x, w = tid >> 5, lane = tid & 31;
    int gid = lane >> 2, tig = lane & 3;
    int m0 = (w & 3) * 16, n0 = (w >> 2) * 32;
    int p0 = pt << 6;

    // phase 1: AqS[p][j] = k1[p][k] @ Wq[q][k][j] (tf32)
    ldA(&g_heads[0][h][p0][0], 64, Atmp, tid);
    ldB(&g_Wq[h][q][0], 64, BsF, tid);
    __syncthreads();
    {
        float accA[4][4] = {};
        wtile(Atmp, BsF, accA, m0, n0, gid, tig);
        __syncthreads();                       // all reads of Atmp/BsF done
#pragma unroll
        for (int nt = 0; nt < 4; nt++) {
            int n = n0 + nt * 8 + 2 * tig;
            AqS[m0 + gid][n]     = to_tf32(accA[nt][0]);
            AqS[m0 + gid][n + 1] = to_tf32(accA[nt][1]);
            AqS[m0 + gid + 8][n]     = to_tf32(accA[nt][2]);
            AqS[m0 + gid + 8][n + 1] = to_tf32(accA[nt][3]);
        }
        __syncthreads();
    }

    // phase 2: loop over t-tiles with online max
    float Mold = -3.0e38f, lsum = 0.0f;
    float tacc[4][4] = {};
    int plo = p0 + m0 + gid, phi = plo + 8;
    for (int tt = 0; tt <= qt; tt++) {
        ldBt(&g_heads[1][h][tt * 64][0], 64, BsF, tid);   // k2 -> BsF (union)
        __syncthreads();
        float sacc[4][4] = {};
        wtile(AqS, BsF, sacc, m0, n0, gid, tig);
        // mask + scale in place; thread-local max
        float tmax = -3.0e38f;
#pragma unroll
        for (int nt = 0; nt < 4; nt++) {
            int t = tt * 64 + n0 + nt * 8 + 2 * tig;
            sacc[nt][0] = (plo > q || t > q)     ? -1e30f : sacc[nt][0] * (1.0f / 64.0f);
            sacc[nt][1] = (plo > q || t + 1 > q) ? -1e30f : sacc[nt][1] * (1.0f / 64.0f);
            sacc[nt][2] = (phi > q || t > q)     ? -1e30f : sacc[nt][2] * (1.0f / 64.0f);
            sacc[nt][3] = (phi > q || t + 1 > q) ? -1e30f : sacc[nt][3] * (1.0f / 64.0f);
            tmax = fmaxf(tmax, fmaxf(fmaxf(sacc[nt][0], sacc[nt][1]),
                                     fmaxf(sacc[nt][2], sacc[nt][3])));
        }
#pragma unroll
        for (int off = 16; off > 0; off >>= 1)
            tmax = fmaxf(tmax, __shfl_xor_sync(0xFFFFFFFFu, tmax, off));
        if (lane == 0) red[w] = tmax;
        __syncthreads();                       // red ready; also: all wtile reads of BsF done
        float Mnew = Mold;
#pragma unroll
        for (int i = 0; i < 8; i++) Mnew = fmaxf(Mnew, red[i]);
        float factor = __expf(Mold - Mnew);
        lsum *= factor;
#pragma unroll
        for (int nt = 0; nt < 4; nt++) {
            tacc[nt][0] *= factor; tacc[nt][1] *= factor;
            tacc[nt][2] *= factor; tacc[nt][3] *= factor;
        }
        // exp + split own fragment -> Ah/Al
#pragma unroll
        for (int nt = 0; nt < 4; nt++) {
            float e00 = __expf(sacc[nt][0] - Mnew), e01 = __expf(sacc[nt][1] - Mnew);
            float e10 = __expf(sacc[nt][2] - Mnew), e11 = __expf(sacc[nt][3] - Mnew);
            lsum += (e00 + e01) + (e10 + e11);
            int kp = (n0 >> 1) + nt * 4 + tig;
            uint32_t hh, ll;
            split_pack(e00, e01, hh, ll); Ah[m0 + gid][kp] = hh;     Al[m0 + gid][kp] = ll;
            split_pack(e10, e11, hh, ll); Ah[m0 + gid + 8][kp] = hh; Al[m0 + gid + 8][kp] = ll;
        }
        ldbfB(&g_heads[4][h][tt * 64][0], 64, Bh, Bl, tid);  // v2 -> union (after sync above)
        __syncthreads();
        wtbf3<72>(Ah, Al, Bh, Bl, tacc, m0, n0, gid, tig);
        __syncthreads();                       // protect union + Ah/Al for next iter
        Mold = Mnew;
    }
    store_tile(&g_T1[h][q][p0][0], 64, tacc, m0, n0, gid, tig);
    // block-reduce lsum -> psum; stripe max -> pmax
#pragma unroll
    for (int off = 16; off > 0; off >>= 1)
        lsum += __shfl_xor_sync(0xFFFFFFFFu, lsum, off);
    if (lane == 0) red[w] = lsum;
    __syncthreads();
    if (tid == 0) {
        float s = 0.0f;
#pragma unroll
        for (int i = 0; i < 8; i++) s += red[i];
        g_psum[h][q][pt] = s;
        g_pmax[h][q][pt] = Mold;
    }
}

// ---- K3 (bf16x3): R[a][c] = sum_p v1[p][a] * T1[p][c], stripe-rescaled -------
__global__ __launch_bounds__(256) void r_kernel() {
    int q = blockIdx.x, h = blockIdx.y;
    int qt = q >> 6;
    extern __shared__ uint32_t smu[];
    uint32_t (*Ah)[36] = reinterpret_cast<uint32_t (*)[36]>(smu + BF_AH);
    uint32_t (*Al)[36] = reinterpret_cast<uint32_t (*)[36]>(smu + BF_AL);
    uint32_t (*Bh)[72] = reinterpret_cast<uint32_t (*)[72]>(smu + BF_BH);
    uint32_t (*Bl)[72] = reinterpret_cast<uint32_t (*)[72]>(smu + BF_BL);
    int tid = threadIdx.x, w = tid >> 5, lane = tid & 31;
    int gid = lane >> 2, tig = lane & 3;
    int m0 = (w & 3) * 16, n0 = (w >> 2) * 32;
    float M = g_pmax[h][q][0];
    for (int pp = 1; pp <= qt; pp++) M = fmaxf(M, g_pmax[h][q][pp]);
    float acc[4][4] = {};
    for (int ks = 0; ks <= qt; ks++) {
        float s = __expf(g_pmax[h][q][ks] - M);
        ldbfAt(&g_heads[3][h][ks * 64][0], 64, Ah, Al, tid);     // v1 [p][a] -> A2[a][ppair]
        ldbfB_s(&g_T1[h][q][ks * 64][0], 64, s, Bh, Bl, tid);    // T1 stripe, rescaled
        __syncthreads();
        wtbf3<72>(Ah, Al, Bh, Bl, acc, m0, n0, gid, tig);
        __syncthreads();
    }
    store_tile(&g_R[h][q][0], 64, acc, m0, n0, gid, tig);
}

// ---------------- K4 (bf16x3): z_part = R @ W_Vq (split-K over ac) ------------
__global__ __launch_bounds__(256) void zp_kernel(const float* __restrict__ WVq) {
    extern __shared__ uint32_t smu[];
    uint32_t (*Ah)[36] = reinterpret_cast<uint32_t (*)[36]>(smu + BF_AH);
    uint32_t (*Al)[36] = reinterpret_cast<uint32_t (*)[36]>(smu + BF_AL);
    uint32_t (*Bh)[72] = reinterpret_cast<uint32_t (*)[72]>(smu + BF_BH);
    uint32_t (*Bl)[72] = reinterpret_cast<uint32_t (*)[72]>(smu + BF_BL);
    int tid = threadIdx.x, w = tid >> 5, lane = tid & 31;
    int gid = lane >> 2, tig = lane & 3;
    int m0 = (w & 3) * 16, n0 = (w >> 2) * 32;
    int sp = blockIdx.x, qt = blockIdx.y, h = blockIdx.z;
    int q0 = qt << 6;
    int ac0 = sp * (4096 / NSPLIT);
    float acc[4][4] = {};
    for (int ks = 0; ks < 4096 / NSPLIT / 64; ks++) {
        ldbfA(&g_R[h][q0][0] + ac0 + ks * 64, 4096, Ah, Al, tid);
        ldbfB(WVq + ((long)h * 4096 + ac0 + ks * 64) * 64, 64, Bh, Bl, tid);
        __syncthreads();
        wtbf3<72>(Ah, Al, Bh, Bl, acc, m0, n0, gid, tig);
        __syncthreads();
    }
    store_tile(&g_zp[sp][h][qt][0][0], 64, acc, m0, n0, gid, tig);
}

// ---------------- K5: reduce split-K, divide by rescaled rowsum ---------------
__global__ __launch_bounds__(256) void zred_kernel() {
    int idx = blockIdx.x * 256 + threadIdx.x;  // 256*512
    int q = idx >> 9, col = idx & 511;
    int h = col >> 6;
    int qt = q >> 6, ql = q & 63;
    int e = col & 63;
    float s = 0.0f;
#pragma unroll
    for (int sp = 0; sp < NSPLIT; sp++) s += g_zp[sp][h][qt][ql][e];
    float M = g_pmax[h][q][0];
    for (int pp = 1; pp <= qt; pp++) M = fmaxf(M, g_pmax[h][q][pp]);
    float rs = 0.0f;
    for (int pp = 0; pp <= qt; pp++) rs += g_psum[h][q][pp] * __expf(g_pmax[h][q][pp] - M);
    g_z[q][col] = s / rs;
}

// ---------------- K6: out = z @ W_out + b_out (fp32 FFMA) ---------------------
__global__ __launch_bounds__(256) void out_kernel(const float* __restrict__ Wout,
                                                  const float* __restrict__ bout,
                                                  float* __restrict__ out) {
    __shared__ float As[64][68];
    __shared__ float Bs[64][68];
    int tid = threadIdx.x, tm = tid >> 4, tn = tid & 15;
    int n0 = blockIdx.x * 64, m0 = blockIdx.y * 64;
    float acc[4][4] = {};
    for (int k0 = 0; k0 < DD; k0 += 64) {
        f_loadAT(&g_z[m0][k0], DD, As, tid);
        f_loadB(Wout + (long)k0 * DD + n0, DD, Bs, tid);
        __syncthreads();
        f_mma(As, Bs, acc, tm, tn);
        __syncthreads();
    }
#pragma unroll
    for (int r = 0; r < 4; r++)
#pragma unroll
        for (int c = 0; c < 4; c++) {
            int row = m0 + tm * 4 + r;
            int col = n0 + tn * 4 + c;
            out[(long)row * DD + col] = acc[r][c] + bout[col];
        }
}

// ---------------- launch ------------------------------------------------------
extern "C" void kernel_launch(void* const* d_in, const int* in_sizes, int n_in,
                              void* d_out, int out_size) {
    const float* x    = (const float*)d_in[0];
    const float* Wkk  = (const float*)d_in[1];
    const float* bkk  = (const float*)d_in[2];
    const float* WKq  = (const float*)d_in[3];
    const float* WVq  = (const float*)d_in[4];
    const float* Wout = (const float*)d_in[5];
    const float* bout = (const float*)d_in[6];
    float* out = (float*)d_out;

    cudaFuncSetAttribute(fused_attn_kernel, cudaFuncAttributeMaxDynamicSharedMemorySize, FU_SMEM);
    cudaFuncSetAttribute(r_kernel,  cudaFuncAttributeMaxDynamicSharedMemorySize, BF_SMEM);
    cudaFuncSetAttribute(zp_kernel, cudaFuncAttributeMaxDynamicSharedMemorySize, BF_SMEM);

    proj_kernel<<<dim3(40, 4), 256>>>(x, Wkk, bkk);
    wq_kernel<<<dim3(64, 4, NH), 256>>>(WKq);
    fused_attn_kernel<<<dim3(4, TT, NH), 256, FU_SMEM>>>();
    r_kernel<<<dim3(TT, NH), 256, BF_SMEM>>>();
    zp_kernel<<<dim3(NSPLIT, 4, NH), 256, BF_SMEM>>>(WVq);
    zred_kernel<<<512, 256>>>();
    out_kernel<<<dim3(8, 4), 256>>>(Wout, bout, out);
}